// round 1
// baseline (speedup 1.0000x reference)
#include <cuda_runtime.h>
#include <cuda_bf16.h>
#include <stdint.h>

#define NN 100000
#define NE 2400000
#define F_HID 32

// ---------------- scratch (device globals; no allocations allowed) ----------
__device__ float g_deg [NN];
__device__ float g_dinv[NN];
__device__ int2  g_edge[NE];
__device__ float g_aggx[NN * 2];
__device__ float g_h1  [NN * F_HID];
__device__ float g_agg2[NN * F_HID];
__device__ float g_z   [NN];
__device__ int   g_is64;

// ---------------- vector reductions (sm_90+) --------------------------------
__device__ __forceinline__ void red_add_v2(float* addr, float a, float b) {
    asm volatile("red.global.add.v2.f32 [%0], {%1, %2};"
                 :: "l"(__cvta_generic_to_global(addr)), "f"(a), "f"(b)
                 : "memory");
}
__device__ __forceinline__ void red_add_v4(float* addr, float a, float b, float c, float d) {
    asm volatile("red.global.add.v4.f32 [%0], {%1, %2, %3, %4};"
                 :: "l"(__cvta_generic_to_global(addr)), "f"(a), "f"(b), "f"(c), "f"(d)
                 : "memory");
}
__device__ __forceinline__ void red_add_f(float* addr, float a) {
    asm volatile("red.global.add.f32 [%0], %1;"
                 :: "l"(__cvta_generic_to_global(addr)), "f"(a)
                 : "memory");
}

// ---------------- K0: detect int64 vs int32 edge_index ----------------------
// int64 values are < 2^31 and non-negative -> every odd 32-bit word is 0.
// For int32 data the odd words are node indices (P(all 256 == 0) ~ 1e-1280).
__global__ void k_detect(const unsigned int* raw) {
    __shared__ unsigned int s;
    if (threadIdx.x == 0) s = 0u;
    __syncthreads();
    unsigned int v = raw[2 * threadIdx.x + 1];
    if (v) atomicOr(&s, v);
    __syncthreads();
    if (threadIdx.x == 0) g_is64 = (s == 0u) ? 1 : 0;
}

// ---------------- K1: init degree with self-loop ----------------------------
__global__ void k_init_deg() {
    int i = blockIdx.x * blockDim.x + threadIdx.x;
    if (i < NN) g_deg[i] = 1.0f;
}

// ---------------- K2: convert edges to int2 + count degree at dst -----------
__global__ void k_edges_deg(const void* raw, int E) {
    int e = blockIdx.x * blockDim.x + threadIdx.x;
    if (e >= E) return;
    int s, d;
    if (g_is64) {
        const long long* p = (const long long*)raw;
        s = (int)p[e];
        d = (int)p[E + e];
    } else {
        const int* p = (const int*)raw;
        s = p[e];
        d = p[E + e];
    }
    g_edge[e] = make_int2(s, d);
    red_add_f(&g_deg[d], 1.0f);
}

// ---------------- K3: dinv + layer-1 self-loop term -------------------------
__global__ void k_dinv_self(const float* __restrict__ x) {
    int i = blockIdx.x * blockDim.x + threadIdx.x;
    if (i >= NN) return;
    float dv = rsqrtf(g_deg[i]);   // deg >= 1 always (self-loop)
    g_dinv[i] = dv;
    float w = dv * dv;
    float2 xv = ((const float2*)x)[i];
    g_aggx[2 * i + 0] = w * xv.x;
    g_aggx[2 * i + 1] = w * xv.y;
}

// ---------------- K4: layer-1 edge scatter (2 floats/edge) ------------------
__global__ void k_scatter1(const float* __restrict__ x, int E) {
    int e = blockIdx.x * blockDim.x + threadIdx.x;
    if (e >= E) return;
    int2 ed = g_edge[e];
    float nrm = g_dinv[ed.x] * g_dinv[ed.y];
    float2 xv = ((const float2*)x)[ed.x];
    red_add_v2(&g_aggx[2 * ed.y], nrm * xv.x, nrm * xv.y);
}

// ---------------- K5: h1 = relu(aggx @ W1 + b1); agg2 self-loop init --------
__global__ void k_h1(const float* __restrict__ W1, const float* __restrict__ b1) {
    int idx = blockIdx.x * blockDim.x + threadIdx.x;   // node*32 + j
    if (idx >= NN * F_HID) return;
    int i = idx >> 5;
    int j = idx & 31;
    float a0 = g_aggx[2 * i + 0];
    float a1 = g_aggx[2 * i + 1];
    float h = fmaf(a0, W1[j], fmaf(a1, W1[F_HID + j], b1[j]));
    h = fmaxf(h, 0.0f);
    g_h1[idx] = h;
    float dv = g_dinv[i];
    g_agg2[idx] = dv * dv * h;
}

// ---------------- K6: layer-2 edge scatter (32 floats/edge, 8 lanes) --------
__global__ void k_scatter2(int E) {
    long long idx = (long long)blockIdx.x * blockDim.x + threadIdx.x;
    if (idx >= (long long)E * 8) return;
    int e = (int)(idx >> 3);
    int f = (int)(idx & 7);
    int2 ed = g_edge[e];
    float nrm = g_dinv[ed.x] * g_dinv[ed.y];
    float4 hv = ((const float4*)(g_h1 + (long long)ed.x * F_HID))[f];
    red_add_v4(&g_agg2[(long long)ed.y * F_HID + f * 4],
               nrm * hv.x, nrm * hv.y, nrm * hv.z, nrm * hv.w);
}

// ---------------- K7: h2 = relu(agg2 @ W2 + b2); z = h2 @ W3; out init ------
__global__ void k_h2z(const float* __restrict__ W2, const float* __restrict__ b2,
                      const float* __restrict__ W3, const float* __restrict__ b3,
                      float* __restrict__ out) {
    __shared__ float sW2[F_HID * F_HID];
    __shared__ float sW3[F_HID];
    for (int t = threadIdx.x; t < F_HID * F_HID; t += blockDim.x) sW2[t] = W2[t];
    if (threadIdx.x < F_HID) sW3[threadIdx.x] = W3[threadIdx.x];
    __syncthreads();

    int warp = threadIdx.x >> 5;
    int lane = threadIdx.x & 31;
    int node = blockIdx.x * (blockDim.x >> 5) + warp;
    if (node >= NN) return;

    float a = g_agg2[node * F_HID + lane];
    float h = b2[lane];
#pragma unroll
    for (int k = 0; k < F_HID; k++)
        h = fmaf(__shfl_sync(0xffffffffu, a, k), sW2[k * F_HID + lane], h);
    h = fmaxf(h, 0.0f);

    float zc = h * sW3[lane];
#pragma unroll
    for (int off = 16; off > 0; off >>= 1)
        zc += __shfl_xor_sync(0xffffffffu, zc, off);

    if (lane == 0) {
        g_z[node] = zc;
        float dv = g_dinv[node];
        out[node] = b3[0] + dv * dv * zc;
    }
}

// ---------------- K8: layer-3 edge scatter (1 float/edge) -------------------
__global__ void k_scatter3(float* __restrict__ out, int E) {
    int e = blockIdx.x * blockDim.x + threadIdx.x;
    if (e >= E) return;
    int2 ed = g_edge[e];
    float nrm = g_dinv[ed.x] * g_dinv[ed.y];
    red_add_f(&out[ed.y], nrm * g_z[ed.x]);
}

// ---------------- launch ----------------------------------------------------
extern "C" void kernel_launch(void* const* d_in, const int* in_sizes, int n_in,
                              void* d_out, int out_size) {
    const float* x  = (const float*)d_in[0];
    const void*  ei = d_in[1];
    const float* W1 = (const float*)d_in[2];
    const float* b1 = (const float*)d_in[3];
    const float* W2 = (const float*)d_in[4];
    const float* b2 = (const float*)d_in[5];
    const float* W3 = (const float*)d_in[6];
    const float* b3 = (const float*)d_in[7];
    float* out = (float*)d_out;

    int E = in_sizes[1] / 2;
    const int B = 256;

    k_detect  <<<1, 256>>>((const unsigned int*)ei);
    k_init_deg<<<(NN + B - 1) / B, B>>>();
    k_edges_deg<<<(E + B - 1) / B, B>>>(ei, E);
    k_dinv_self<<<(NN + B - 1) / B, B>>>(x);
    k_scatter1 <<<(E + B - 1) / B, B>>>(x, E);
    k_h1       <<<(NN * F_HID + B - 1) / B, B>>>(W1, b1);
    {
        long long total = (long long)E * 8;
        int blocks = (int)((total + B - 1) / B);
        k_scatter2<<<blocks, B>>>(E);
    }
    k_h2z      <<<(NN + 7) / 8, 256>>>(W2, b2, W3, b3, out);
    k_scatter3 <<<(E + B - 1) / B, B>>>(out, E);
}